// round 1
// baseline (speedup 1.0000x reference)
#include <cuda_runtime.h>
#include <float.h>

#define NA 8400
#define NB 64
#define NC 32
#define MAXD 100
#define CONF_T 0.25f
#define IOU_T 0.45f
#define NTHREADS 1024

// Dynamic smem layout: scores[NA], y1[NA], x1[NA], y2[NA], x2[NA] (floats), cls[NA] (u8)
#define SMEM_BYTES (5 * NA * sizeof(float) + NA)

__global__ __launch_bounds__(NTHREADS, 1)
void yolo_nms_kernel(const float* __restrict__ in, float* __restrict__ out)
{
    extern __shared__ float smem[];
    float* s_sc = smem;
    float* s_y1 = s_sc + NA;
    float* s_x1 = s_y1 + NA;
    float* s_y2 = s_x1 + NA;
    float* s_x2 = s_y2 + NA;
    unsigned char* s_cls = (unsigned char*)(s_x2 + NA);

    __shared__ float r_val[32];
    __shared__ int   r_idx[32];
    __shared__ float pick_val;
    __shared__ int   pick_idx;

    const int b   = blockIdx.x;
    const int tid = threadIdx.x;
    const int bs  = blockDim.x;
    const float* base = in + (size_t)b * (4 + NC) * NA;

    float* out_boxes = out;                               // [NB, MAXD, 4]
    float* out_cls   = out + (size_t)NB * MAXD * 4;       // [NB, MAXD]
    float* out_scr   = out_cls + (size_t)NB * MAXD;       // [NB, MAXD]
    float* out_num   = out_scr + (size_t)NB * MAXD;       // [NB]

    // ---- Phase 1: per-anchor class max/argmax + corner decode (coalesced) ----
    for (int a = tid; a < NA; a += bs) {
        float xc = base[0 * NA + a];
        float yc = base[1 * NA + a];
        float w  = base[2 * NA + a];
        float h  = base[3 * NA + a];
        float best = -FLT_MAX;
        int   bc   = 0;
        #pragma unroll
        for (int k = 0; k < NC; ++k) {
            float v = base[(4 + k) * NA + a];
            if (v > best) { best = v; bc = k; }   // strict > => first max index
        }
        s_sc[a]  = (best >= CONF_T) ? best : -1.0f;
        s_cls[a] = (unsigned char)bc;
        float hh = h * 0.5f, hw = w * 0.5f;
        s_y1[a] = fminf(fmaxf(yc - hh, 0.0f), 1.0f);
        s_x1[a] = fminf(fmaxf(xc - hw, 0.0f), 1.0f);
        s_y2[a] = fminf(fmaxf(yc + hh, 0.0f), 1.0f);
        s_x2[a] = fminf(fmaxf(xc + hw, 0.0f), 1.0f);
    }
    __syncthreads();

    // ---- Phase 2: greedy NMS, 100 sequential iterations ----
    int it;
    for (it = 0; it < MAXD; ++it) {
        // local argmax (per-thread candidate already holds its min index for ties)
        float bv = -FLT_MAX;
        int   bi = 0x7fffffff;
        for (int a = tid; a < NA; a += bs) {
            float v = s_sc[a];
            if (v > bv) { bv = v; bi = a; }
        }
        // warp-level argmax reduce with min-index tie-break
        #pragma unroll
        for (int off = 16; off > 0; off >>= 1) {
            float ov = __shfl_down_sync(0xffffffffu, bv, off);
            int   oi = __shfl_down_sync(0xffffffffu, bi, off);
            if (ov > bv || (ov == bv && oi < bi)) { bv = ov; bi = oi; }
        }
        const int warp = tid >> 5;
        if ((tid & 31) == 0) { r_val[warp] = bv; r_idx[warp] = bi; }
        __syncthreads();
        if (warp == 0) {
            const int nw = bs >> 5;
            float v2 = (tid < nw) ? r_val[tid] : -FLT_MAX;
            int   i2 = (tid < nw) ? r_idx[tid] : 0x7fffffff;
            #pragma unroll
            for (int off = 16; off > 0; off >>= 1) {
                float ov = __shfl_down_sync(0xffffffffu, v2, off);
                int   oi = __shfl_down_sync(0xffffffffu, i2, off);
                if (ov > v2 || (ov == v2 && oi < i2)) { v2 = ov; i2 = oi; }
            }
            if (tid == 0) { pick_val = v2; pick_idx = i2; }
        }
        __syncthreads();

        const float pv = pick_val;
        const int   pi = pick_idx;

        if (pv <= 0.0f) {
            // scores only decrease -> all remaining slots are zeros (exact early-exit)
            for (int i = it * 4 + tid; i < MAXD * 4; i += bs)
                out_boxes[(size_t)b * MAXD * 4 + i] = 0.0f;
            for (int i = it + tid; i < MAXD; i += bs) {
                out_cls[(size_t)b * MAXD + i] = 0.0f;
                out_scr[(size_t)b * MAXD + i] = 0.0f;
            }
            if (tid == 0) out_num[b] = (float)it;
            break;
        }

        const float by1 = s_y1[pi], bx1 = s_x1[pi];
        const float by2 = s_y2[pi], bx2 = s_x2[pi];
        const float area_a = (by2 - by1) * (bx2 - bx1);

        for (int a = tid; a < NA; a += bs) {
            float ay1 = s_y1[a], ax1 = s_x1[a], ay2 = s_y2[a], ax2 = s_x2[a];
            float y1 = fmaxf(by1, ay1);
            float x1 = fmaxf(bx1, ax1);
            float y2 = fminf(by2, ay2);
            float x2 = fminf(bx2, ax2);
            float inter  = fmaxf(y2 - y1, 0.0f) * fmaxf(x2 - x1, 0.0f);
            float area_b = (ay2 - ay1) * (ax2 - ax1);
            float uni    = area_a + area_b - inter;
            float iou    = (uni > 0.0f) ? (inter / uni) : 0.0f;
            if (iou > IOU_T) s_sc[a] = -1.0f;
        }
        if (tid == 0) {
            s_sc[pi] = -1.0f;   // explicit self-suppress (self-IoU may be 0 for degenerate boxes)
            float* ob = out_boxes + ((size_t)b * MAXD + it) * 4;
            ob[0] = by1; ob[1] = bx1; ob[2] = by2; ob[3] = bx2;
            out_cls[(size_t)b * MAXD + it] = (float)s_cls[pi];
            out_scr[(size_t)b * MAXD + it] = pv;
        }
        __syncthreads();
    }
    if (it == MAXD && tid == 0) out_num[b] = (float)MAXD;
}

extern "C" void kernel_launch(void* const* d_in, const int* in_sizes, int n_in,
                              void* d_out, int out_size)
{
    (void)in_sizes; (void)n_in; (void)out_size;
    const float* in = (const float*)d_in[0];
    float* out = (float*)d_out;

    cudaFuncSetAttribute(yolo_nms_kernel,
                         cudaFuncAttributeMaxDynamicSharedMemorySize,
                         (int)SMEM_BYTES);
    yolo_nms_kernel<<<NB, NTHREADS, SMEM_BYTES>>>(in, out);
}

// round 2
// speedup vs baseline: 1.1460x; 1.1460x over previous
#include <cuda_runtime.h>
#include <float.h>

#define NA 8400
#define NB 64
#define NC 32
#define MAXD 100
#define CONF_T 0.25f
#define IOU_T 0.45f
#define NT 1024
#define NW 32
#define SEG_CAP 288
#define TRIPS1 ((NA + NT - 1) / NT)   // 9

// dynamic smem: float4 box[NA] | float sc[NA] | u16 seg[2][NW*SEG_CAP] | u8 cls[NA]
#define SM_BOX_B (NA * 16)
#define SM_SC_B  (NA * 4)
#define SM_SEG_B (2 * NW * SEG_CAP * 2)
#define SM_CLS_B (NA)
#define SMEM_BYTES (SM_BOX_B + SM_SC_B + SM_SEG_B + SM_CLS_B)

__global__ __launch_bounds__(NT, 1)
void yolo_nms_kernel(const float* __restrict__ in, float* __restrict__ out)
{
    extern __shared__ unsigned char smem_raw[];
    float4*         s_box = (float4*)smem_raw;
    float*          s_sc  = (float*)(smem_raw + SM_BOX_B);
    unsigned short* s_seg = (unsigned short*)(smem_raw + SM_BOX_B + SM_SC_B);
    unsigned char*  s_cls = (unsigned char*)(smem_raw + SM_BOX_B + SM_SC_B + SM_SEG_B);

    __shared__ float r_val[NW];
    __shared__ int   r_idx[NW];
    __shared__ float s_pv;
    __shared__ int   s_pi;

    const int b    = blockIdx.x;
    const int tid  = threadIdx.x;
    const int lane = tid & 31;
    const int w    = tid >> 5;
    const unsigned lt_mask = (1u << lane) - 1u;
    const float* base = in + (size_t)b * (4 + NC) * NA;

    float* out_boxes = out;                          // [NB, MAXD, 4]
    float* out_cls   = out + (size_t)NB * MAXD * 4;  // [NB, MAXD]
    float* out_scr   = out_cls + (size_t)NB * MAXD;  // [NB, MAXD]
    float* out_num   = out_scr + (size_t)NB * MAXD;  // [NB]

    int cur  = 0;
    int nseg = 0;                     // per-warp live count (uniform within warp)
    float bv = -FLT_MAX;              // local argmax accumulator
    int   bi = 0x7fffffff;

    // ---- Phase 1: decode + conf-filter + build per-warp live segments + first argmax ----
    #pragma unroll
    for (int t = 0; t < TRIPS1; ++t) {
        int a  = tid + t * NT;
        bool va = (a < NA);
        int aa = va ? a : 0;
        float xc = base[0 * NA + aa];
        float yc = base[1 * NA + aa];
        float ww = base[2 * NA + aa];
        float hh = base[3 * NA + aa];
        float best = -FLT_MAX; int bc = 0;
        #pragma unroll
        for (int k = 0; k < NC; ++k) {
            float v = base[(4 + k) * NA + aa];
            if (v > best) { best = v; bc = k; }   // strict > => first max index
        }
        float h2 = hh * 0.5f, w2 = ww * 0.5f;
        float4 bx;
        bx.x = fminf(fmaxf(yc - h2, 0.0f), 1.0f);
        bx.y = fminf(fmaxf(xc - w2, 0.0f), 1.0f);
        bx.z = fminf(fmaxf(yc + h2, 0.0f), 1.0f);
        bx.w = fminf(fmaxf(xc + w2, 0.0f), 1.0f);
        if (va) {
            s_box[a]  = bx;
            s_sc[a]   = best;
            s_cls[a]  = (unsigned char)bc;
        }
        bool keep = va && (best >= CONF_T);
        unsigned m = __ballot_sync(0xffffffffu, keep);
        if (keep) {
            s_seg[cur * (NW * SEG_CAP) + w * SEG_CAP + nseg + __popc(m & lt_mask)] =
                (unsigned short)a;
            if (best > bv) { bv = best; bi = a; }   // per-lane indices ascending
        }
        nseg += __popc(m);
    }
    __syncthreads();

    // ---- Phase 2: greedy NMS with fused suppress+compact+argmax ----
    for (int it = 0; ; ++it) {
        // block argmax reduce of (bv, bi) with min-index tie-break
        #pragma unroll
        for (int off = 16; off > 0; off >>= 1) {
            float ov = __shfl_down_sync(0xffffffffu, bv, off);
            int   oi = __shfl_down_sync(0xffffffffu, bi, off);
            if (ov > bv || (ov == bv && oi < bi)) { bv = ov; bi = oi; }
        }
        if (lane == 0) { r_val[w] = bv; r_idx[w] = bi; }
        __syncthreads();
        if (w == 0) {
            float v2 = r_val[lane];
            int   i2 = r_idx[lane];
            #pragma unroll
            for (int off = 16; off > 0; off >>= 1) {
                float ov = __shfl_down_sync(0xffffffffu, v2, off);
                int   oi = __shfl_down_sync(0xffffffffu, i2, off);
                if (ov > v2 || (ov == v2 && oi < i2)) { v2 = ov; i2 = oi; }
            }
            if (lane == 0) { s_pv = v2; s_pi = i2; }
        }
        __syncthreads();
        const float pv = s_pv;
        const int   pi = s_pi;

        if (pv <= 0.0f) {   // live set empty: remaining slots are exact zeros
            for (int i = it * 4 + tid; i < MAXD * 4; i += NT)
                out_boxes[(size_t)b * MAXD * 4 + i] = 0.0f;
            for (int i = it + tid; i < MAXD; i += NT) {
                out_cls[(size_t)b * MAXD + i] = 0.0f;
                out_scr[(size_t)b * MAXD + i] = 0.0f;
            }
            if (tid == 0) out_num[b] = (float)it;
            return;
        }

        float4 pb = s_box[pi];   // broadcast LDS (uniform index, conflict-free)
        if (tid == 0) {
            float* ob = out_boxes + ((size_t)b * MAXD + it) * 4;
            ob[0] = pb.x; ob[1] = pb.y; ob[2] = pb.z; ob[3] = pb.w;
            out_cls[(size_t)b * MAXD + it] = (float)s_cls[pi];
            out_scr[(size_t)b * MAXD + it] = pv;
        }
        if (it == MAXD - 1) {
            if (tid == 0) out_num[b] = (float)MAXD;
            return;
        }

        // fused pass over this warp's live segment:
        // suppress vs pick, compact survivors into the other buffer, track next argmax
        const float area_a = (pb.z - pb.x) * (pb.w - pb.y);
        bv = -FLT_MAX; bi = 0x7fffffff;
        const int nxt = cur ^ 1;
        int newn = 0;
        const int trips = (nseg + 31) >> 5;
        const unsigned short* __restrict__ src = s_seg + cur * (NW * SEG_CAP) + w * SEG_CAP;
        unsigned short*       __restrict__ dst = s_seg + nxt * (NW * SEG_CAP) + w * SEG_CAP;
        for (int t = 0; t < trips; ++t) {
            int  j  = lane + t * 32;
            bool vj = (j < nseg);
            int idx = vj ? (int)src[j] : 0;       // clamp stale slots to a safe index
            float4 bb = s_box[idx];
            float y1 = fmaxf(pb.x, bb.x);
            float x1 = fmaxf(pb.y, bb.y);
            float y2 = fminf(pb.z, bb.z);
            float x2 = fminf(pb.w, bb.w);
            float inter  = fmaxf(y2 - y1, 0.0f) * fmaxf(x2 - x1, 0.0f);
            float area_b = (bb.z - bb.x) * (bb.w - bb.y);
            float uni    = area_a + area_b - inter;
            float iou    = (uni > 0.0f) ? (inter / uni) : 0.0f;   // bitwise same as reference
            bool keep = vj && (idx != pi) && !(iou > IOU_T);
            unsigned m = __ballot_sync(0xffffffffu, keep);
            if (keep) {
                dst[newn + __popc(m & lt_mask)] = (unsigned short)idx;
                float sc = s_sc[idx];
                if (sc > bv || (sc == bv && idx < bi)) { bv = sc; bi = idx; }
            }
            newn += __popc(m);
        }
        nseg = newn;
        cur  = nxt;
        // no barrier needed: seg buffers are warp-private; reduction barriers follow
    }
}

extern "C" void kernel_launch(void* const* d_in, const int* in_sizes, int n_in,
                              void* d_out, int out_size)
{
    (void)in_sizes; (void)n_in; (void)out_size;
    const float* in = (const float*)d_in[0];
    float* out = (float*)d_out;

    cudaFuncSetAttribute(yolo_nms_kernel,
                         cudaFuncAttributeMaxDynamicSharedMemorySize,
                         (int)SMEM_BYTES);
    yolo_nms_kernel<<<NB, NT, SMEM_BYTES>>>(in, out);
}